// round 3
// baseline (speedup 1.0000x reference)
#include <cuda_runtime.h>
#include <cstdint>
#include <math.h>

// ---------------------------------------------------------------------------
// Problem constants
// ---------------------------------------------------------------------------
namespace cfg {
constexpr int B   = 64;
constexpr int T   = 256;
constexpr int E   = 300;
constexpr int H   = 200;
constexpr int BT  = B * T;        // 16384
constexpr int G4  = 4 * H;        // 800
constexpr int ENC = 2 * H;        // 400
constexpr long TT  = (long)T * T; // 65536
constexpr int BB  = 4;            // batch elems per LSTM block
}
using namespace cfg;

// ---------------------------------------------------------------------------
// Static device scratch (allocation-free rule: __device__ globals)
// ---------------------------------------------------------------------------
__device__ float d_ebuf [2L * BT * E];          // embedded inputs        ~39 MB
__device__ float d_Gproj[2L * BT * (2 * G4)];   // input gate projections ~210 MB (reused by layer 2)
__device__ float d_xh   [2L * BT * ENC];        // layer-1 BiLSTM outputs ~52 MB
__device__ float d_xcomp[2L * BT * ENC];        // layer-2 BiLSTM outputs ~52 MB
__device__ float d_xal  [2L * BT * ENC];        // alignments             ~52 MB
__device__ float d_xc   [2L * BT * H];          // projected inputs (L2)  ~26 MB
__device__ float d_P    [(long)B * T * T];      // Dykstra p / scores     ~67 MB
__device__ float d_Q1   [(long)B * T * T];
__device__ float d_Q2T  [(long)B * T * T];
__device__ float d_Ybuf [(long)B * T * T];
__device__ float d_YT   [(long)B * T * T];
__device__ float d_rep  [B * 4 * ENC];

// ---------------------------------------------------------------------------
// Generic tiled SGEMM.  NT: C = A[M,K] @ B[N,K]^T.  NN: C = A[M,K] @ B[K,N].
// Optional batch strides, accumulate into C, bias (per column), ReLU.
// ---------------------------------------------------------------------------
template <int BM, int BN, int BK, int TM, int TN, bool NT>
__global__ void sgemm_kernel(int M, int N, int K,
                             const float* __restrict__ A, int lda, long sA,
                             const float* __restrict__ Bm, int ldb, long sB,
                             float* __restrict__ C, int ldc, long sC,
                             const float* __restrict__ bias, int relu, int accum)
{
    constexpr int TX = BN / TN;
    constexpr int TY = BM / TM;
    static_assert(TX * TY == 256, "256 threads");
    __shared__ float As[BK][BM];
    __shared__ float Bs[BK][BN];

    int tid = threadIdx.x;
    int tx = tid % TX, ty = tid / TX;
    int m0 = blockIdx.y * BM, n0 = blockIdx.x * BN;
    A  += (long)blockIdx.z * sA;
    Bm += (long)blockIdx.z * sB;
    C  += (long)blockIdx.z * sC;

    float acc[TM][TN];
#pragma unroll
    for (int i = 0; i < TM; i++)
#pragma unroll
        for (int j = 0; j < TN; j++) acc[i][j] = 0.f;

    for (int k0 = 0; k0 < K; k0 += BK) {
        for (int idx = tid; idx < BM * BK; idx += 256) {
            int m = idx / BK, kk = idx % BK;
            int gm = m0 + m, gk = k0 + kk;
            As[kk][m] = (gm < M && gk < K) ? A[(long)gm * lda + gk] : 0.f;
        }
        if (NT) {
            for (int idx = tid; idx < BN * BK; idx += 256) {
                int n = idx / BK, kk = idx % BK;
                int gn = n0 + n, gk = k0 + kk;
                Bs[kk][n] = (gn < N && gk < K) ? Bm[(long)gn * ldb + gk] : 0.f;
            }
        } else {
            for (int idx = tid; idx < BN * BK; idx += 256) {
                int n = idx % BN, kk = idx / BN;
                int gn = n0 + n, gk = k0 + kk;
                Bs[kk][n] = (gn < N && gk < K) ? Bm[(long)gk * ldb + gn] : 0.f;
            }
        }
        __syncthreads();
#pragma unroll
        for (int kk = 0; kk < BK; kk++) {
            float ra[TM], rb[TN];
#pragma unroll
            for (int i = 0; i < TM; i++) ra[i] = As[kk][ty * TM + i];
#pragma unroll
            for (int j = 0; j < TN; j++) rb[j] = Bs[kk][tx * TN + j];
#pragma unroll
            for (int i = 0; i < TM; i++)
#pragma unroll
                for (int j = 0; j < TN; j++) acc[i][j] = fmaf(ra[i], rb[j], acc[i][j]);
        }
        __syncthreads();
    }

#pragma unroll
    for (int i = 0; i < TM; i++) {
        int gm = m0 + ty * TM + i;
        if (gm >= M) continue;
#pragma unroll
        for (int j = 0; j < TN; j++) {
            int gn = n0 + tx * TN + j;
            if (gn >= N) continue;
            float v = acc[i][j];
            long ci = (long)gm * ldc + gn;
            if (accum) v += C[ci];
            if (bias)  v += bias[gn];
            if (relu)  v = fmaxf(v, 0.f);
            C[ci] = v;
        }
    }
}

// ---------------------------------------------------------------------------
// Elementwise / small kernels
// ---------------------------------------------------------------------------
__global__ void embed_kernel(const int* __restrict__ x1, const int* __restrict__ x2,
                             const float* __restrict__ emb, float* __restrict__ ebuf)
{
    long idx = (long)blockIdx.x * blockDim.x + threadIdx.x;
    if (idx >= 2L * BT * E) return;
    int e = (int)(idx % E);
    long bt = (idx / E) % BT;
    int s = (int)(idx / ((long)E * BT));
    int tok = s ? x2[bt] : x1[bt];
    ebuf[idx] = emb[(long)tok * E + e];
}

__device__ __forceinline__ float sigmf(float x) { return 1.f / (1.f + expf(-x)); }

// ---------------------------------------------------------------------------
// Persistent fused BiLSTM layer.
// Grid: (64/BB, 2 dirs, 2 seqs), 256 threads.
// Each block owns BB batch rows of one (seq, dir): runs all T steps with
// h/c/gates in shared memory; Whh read from L2 (both dir matrices ~1.3 MB,
// L2-resident across 64 blocks). Input projections precomputed in Gproj.
// ---------------------------------------------------------------------------
__global__ __launch_bounds__(256, 4)
void lstm_layer_kernel(const float* __restrict__ Gproj,
                       const float* __restrict__ Wf,
                       const float* __restrict__ Wb,
                       float* __restrict__ xh_out)
{
    __shared__ float h_s[BB][H];
    __shared__ float c_s[BB][H];
    __shared__ float g_s[BB][G4];

    int tid = threadIdx.x;
    int b0  = blockIdx.x * BB;
    int d   = blockIdx.y;
    int s   = blockIdx.z;
    const float* W = d ? Wb : Wf;

    for (int i = tid; i < BB * H; i += 256) {
        (&h_s[0][0])[i] = 0.f;
        (&c_s[0][0])[i] = 0.f;
    }
    __syncthreads();

    for (int t = 0; t < T; t++) {
        int ta = d ? (T - 1 - t) : t;
        // per-batch-row base into Gproj for this timestep
        long gb0 = ((long)s * BT + (long)(b0 + 0) * T + ta) * (2 * G4) + (long)d * G4;
        long gb1 = ((long)s * BT + (long)(b0 + 1) * T + ta) * (2 * G4) + (long)d * G4;
        long gb2 = ((long)s * BT + (long)(b0 + 2) * T + ta) * (2 * G4) + (long)d * G4;
        long gb3 = ((long)s * BT + (long)(b0 + 3) * T + ta) * (2 * G4) + (long)d * G4;

        // gates[g] = Whh[g,:] . h  + Gproj
        for (int g = tid; g < G4; g += 256) {
            const float4* w4 = reinterpret_cast<const float4*>(W + (long)g * H);
            float a0 = 0.f, a1 = 0.f, a2 = 0.f, a3 = 0.f;
#pragma unroll
            for (int k4 = 0; k4 < H / 4; k4++) {
                float4 w = w4[k4];
                int k = 4 * k4;
                a0 += w.x * h_s[0][k] + w.y * h_s[0][k + 1] + w.z * h_s[0][k + 2] + w.w * h_s[0][k + 3];
                a1 += w.x * h_s[1][k] + w.y * h_s[1][k + 1] + w.z * h_s[1][k + 2] + w.w * h_s[1][k + 3];
                a2 += w.x * h_s[2][k] + w.y * h_s[2][k + 1] + w.z * h_s[2][k + 2] + w.w * h_s[2][k + 3];
                a3 += w.x * h_s[3][k] + w.y * h_s[3][k + 1] + w.z * h_s[3][k + 2] + w.w * h_s[3][k + 3];
            }
            g_s[0][g] = a0 + Gproj[gb0 + g];
            g_s[1][g] = a1 + Gproj[gb1 + g];
            g_s[2][g] = a2 + Gproj[gb2 + g];
            g_s[3][g] = a3 + Gproj[gb3 + g];
        }
        __syncthreads();

        // state update (h_s writes are safe: gate-phase reads finished above)
        for (int i = tid; i < BB * H; i += 256) {
            int b = i / H, hh = i % H;
            float gi = g_s[b][hh];
            float gf = g_s[b][H + hh];
            float gg = g_s[b][2 * H + hh];
            float go = g_s[b][3 * H + hh];
            float cn = sigmf(gf) * c_s[b][hh] + sigmf(gi) * tanhf(gg);
            float hn = sigmf(go) * tanhf(cn);
            c_s[b][hh] = cn;
            h_s[b][hh] = hn;
            xh_out[((long)s * BT + (long)(b0 + b) * T + ta) * ENC + d * H + hh] = hn;
        }
        __syncthreads();
    }
}

// ---------------------------------------------------------------------------
// Capped-simplex row projection (mirrors reference math exactly).
// One block of 256 threads per row of length T=256.
// ---------------------------------------------------------------------------
__global__ void proj_row_kernel(const float* __restrict__ P,
                                const float* __restrict__ Qin,
                                float* __restrict__ Y,
                                float* __restrict__ Qout,
                                int use_q)
{
    __shared__ float srt[T];
    __shared__ float cs[T];
    __shared__ float warp_s[8];
    __shared__ int   warp_c[8];
    __shared__ float sh_tau;

    int row = blockIdx.x;
    int j = threadIdx.x;
    long off = (long)row * T + j;

    float val = P[off];
    if (use_q) val += Qin[off];
    srt[j] = val;
    __syncthreads();

    // bitonic sort, descending
    for (int k = 2; k <= T; k <<= 1) {
        for (int jj = k >> 1; jj > 0; jj >>= 1) {
            int l = j ^ jj;
            if (l > j) {
                float a = srt[j], b2 = srt[l];
                bool desc = ((j & k) == 0);
                if (desc ? (a < b2) : (a > b2)) { srt[j] = b2; srt[l] = a; }
            }
            __syncthreads();
        }
    }

    // inclusive cumsum of sorted values
    cs[j] = srt[j];
    __syncthreads();
    for (int o = 1; o < T; o <<= 1) {
        float tv = (j >= o) ? cs[j - o] : 0.f;
        __syncthreads();
        cs[j] += tv;
        __syncthreads();
    }

    // kmax = count(1 + k*z_k > cz_k),  ssum = sum(max(v,0))
    int lane = j & 31, wid = j >> 5;
    float u = fmaxf(val, 0.f);
#pragma unroll
    for (int o = 16; o; o >>= 1) u += __shfl_down_sync(0xffffffffu, u, o);
    bool fl = (1.f + (float)(j + 1) * srt[j]) > cs[j];
    unsigned bal = __ballot_sync(0xffffffffu, fl);
    if (lane == 0) { warp_s[wid] = u; warp_c[wid] = __popc(bal); }
    __syncthreads();
    if (j == 0) {
        float ssum = 0.f; int kmax = 0;
#pragma unroll
        for (int w = 0; w < 8; w++) { ssum += warp_s[w]; kmax += warp_c[w]; }
        float tau = 0.f;
        if (ssum > 1.f) tau = (cs[kmax - 1] - 1.f) / (float)kmax;
        sh_tau = tau;
    }
    __syncthreads();

    float y = fmaxf(val - sh_tau, 0.f);
    Y[off] = y;
    Qout[off] = val - y;
}

// batched transpose of the last two dims of [B,T,T]
__global__ void transpose_kernel(const float* __restrict__ in, float* __restrict__ out)
{
    __shared__ float tile[32][33];
    long base = (long)blockIdx.z * TT;
    int i0 = blockIdx.y * 32, j0 = blockIdx.x * 32;
#pragma unroll
    for (int r = 0; r < 4; r++) {
        int i = i0 + threadIdx.y + r * 8;
        tile[threadIdx.y + r * 8][threadIdx.x] = in[base + (long)i * T + j0 + threadIdx.x];
    }
    __syncthreads();
#pragma unroll
    for (int r = 0; r < 4; r++) {
        int jj = j0 + threadIdx.y + r * 8;
        out[base + (long)jj * T + i0 + threadIdx.x] = tile[threadIdx.x][threadIdx.y + r * 8];
    }
}

__global__ void pool_kernel(const float* __restrict__ xcomp, float* __restrict__ rep)
{
    int idx = blockIdx.x * blockDim.x + threadIdx.x;
    if (idx >= 2 * B * ENC) return;
    int f = idx % ENC;
    int b = (idx / ENC) % B;
    int s = idx / (ENC * B);
    const float* base = xcomp + ((long)s * BT + (long)b * T) * ENC + f;
    float mx = -3.4e38f, sm = 0.f;
    for (int t = 0; t < T; t++) {
        float v = base[(long)t * ENC];
        sm += v;
        mx = fmaxf(mx, v);
    }
    rep[(long)b * (4 * ENC) + s * (2 * ENC) + f]       = sm * (1.f / (float)T);
    rep[(long)b * (4 * ENC) + s * (2 * ENC) + ENC + f] = mx;
}

__global__ void final_kernel(const float* __restrict__ rep, const float* __restrict__ Wo,
                             const float* __restrict__ bo, float* __restrict__ out)
{
    __shared__ float red[256];
    int b = blockIdx.x, tid = threadIdx.x;
    float s = 0.f;
    for (int i = tid; i < 4 * ENC; i += 256) s += rep[(long)b * (4 * ENC) + i] * Wo[i];
    red[tid] = s;
    __syncthreads();
    for (int o = 128; o; o >>= 1) {
        if (tid < o) red[tid] += red[tid + o];
        __syncthreads();
    }
    if (tid == 0) out[(long)B * TT + b] = 1.f / (1.f + expf(-(red[0] + bo[0])));
}

// ---------------------------------------------------------------------------
// Host launch helpers
// ---------------------------------------------------------------------------
static void gemm_nt_big(int M, int N, int K,
                        const float* A, int lda, long sA,
                        const float* Bm, int ldb, long sB,
                        float* C, int ldc, long sC,
                        const float* bias, int relu, int accum, int batch)
{
    dim3 grid((N + 63) / 64, (M + 127) / 128, batch);
    sgemm_kernel<128, 64, 16, 8, 4, true><<<grid, 256>>>(M, N, K, A, lda, sA, Bm, ldb, sB, C, ldc, sC, bias, relu, accum);
}
static void gemm_nn_big(int M, int N, int K,
                        const float* A, int lda, long sA,
                        const float* Bm, int ldb, long sB,
                        float* C, int ldc, long sC,
                        const float* bias, int relu, int accum, int batch)
{
    dim3 grid((N + 63) / 64, (M + 127) / 128, batch);
    sgemm_kernel<128, 64, 16, 8, 4, false><<<grid, 256>>>(M, N, K, A, lda, sA, Bm, ldb, sB, C, ldc, sC, bias, relu, accum);
}

// ---------------------------------------------------------------------------
// kernel_launch
// ---------------------------------------------------------------------------
extern "C" void kernel_launch(void* const* d_in, const int* in_sizes, int n_in,
                              void* d_out, int out_size)
{
    const int*   x1     = (const int*)d_in[0];
    const int*   x2     = (const int*)d_in[1];
    const float* embed  = (const float*)d_in[4];
    const float* Wih_cf = (const float*)d_in[5];
    const float* Whh_cf = (const float*)d_in[6];
    const float* b_cf   = (const float*)d_in[7];
    const float* Wih_cb = (const float*)d_in[8];
    const float* Whh_cb = (const float*)d_in[9];
    const float* b_cb   = (const float*)d_in[10];
    const float* Wp1    = (const float*)d_in[11];
    const float* bp1    = (const float*)d_in[12];
    const float* Wp2    = (const float*)d_in[13];
    const float* bp2    = (const float*)d_in[14];
    const float* Wih_mf = (const float*)d_in[15];
    const float* Whh_mf = (const float*)d_in[16];
    const float* b_mf   = (const float*)d_in[17];
    const float* Wih_mb = (const float*)d_in[18];
    const float* Whh_mb = (const float*)d_in[19];
    const float* b_mb   = (const float*)d_in[20];
    const float* Wo     = (const float*)d_in[21];
    const float* bo     = (const float*)d_in[22];
    float* out = (float*)d_out;

    void* p;
    cudaGetSymbolAddress(&p, d_ebuf);  float* ebuf  = (float*)p;
    cudaGetSymbolAddress(&p, d_Gproj); float* Gproj = (float*)p;
    cudaGetSymbolAddress(&p, d_xh);    float* xh    = (float*)p;
    cudaGetSymbolAddress(&p, d_xcomp); float* xcomp = (float*)p;
    cudaGetSymbolAddress(&p, d_xal);   float* xal   = (float*)p;
    cudaGetSymbolAddress(&p, d_xc);    float* xc    = (float*)p;
    cudaGetSymbolAddress(&p, d_P);     float* Pb    = (float*)p;
    cudaGetSymbolAddress(&p, d_Q1);    float* Q1    = (float*)p;
    cudaGetSymbolAddress(&p, d_Q2T);   float* Q2T   = (float*)p;
    cudaGetSymbolAddress(&p, d_Ybuf);  float* Yb    = (float*)p;
    cudaGetSymbolAddress(&p, d_YT);    float* YTb   = (float*)p;
    cudaGetSymbolAddress(&p, d_rep);   float* rep   = (float*)p;

    // ---- Embedding gather ----
    {
        long n = 2L * BT * E;
        embed_kernel<<<(int)((n + 255) / 256), 256>>>(x1, x2, embed, ebuf);
    }

    // ---- Layer-1 input projections: Gproj[s][bt][d*800 + g] ----
    for (int s = 0; s < 2; s++) {
        gemm_nt_big(BT, G4, E, ebuf + (long)s * BT * E, E, 0,
                    Wih_cf, E, 0,
                    Gproj + (long)s * BT * (2 * G4), 2 * G4, 0, b_cf, 0, 0, 1);
        gemm_nt_big(BT, G4, E, ebuf + (long)s * BT * E, E, 0,
                    Wih_cb, E, 0,
                    Gproj + (long)s * BT * (2 * G4) + G4, 2 * G4, 0, b_cb, 0, 0, 1);
    }

    // ---- BiLSTM layer 1 (single persistent kernel) ----
    {
        dim3 grid(B / BB, 2, 2);
        lstm_layer_kernel<<<grid, 256>>>(Gproj, Whh_cf, Whh_cb, xh);
    }

    // ---- Scores: batched x1_h @ x2_h^T -> d_P ----
    gemm_nt_big(T, T, ENC,
                xh, ENC, (long)T * ENC,
                xh + (long)BT * ENC, ENC, (long)T * ENC,
                Pb, T, TT, nullptr, 0, 0, B);

    // ---- Dykstra (10 iterations) ----
    dim3 tgrid(8, 8, B), tblk(32, 8);
    for (int it = 0; it < 10; it++) {
        proj_row_kernel<<<BT, 256>>>(Pb, Q1, Yb, Q1, it > 0);
        transpose_kernel<<<tgrid, tblk>>>(Yb, YTb);
        proj_row_kernel<<<BT, 256>>>(YTb, Q2T, Yb, Q2T, it > 0);   // Yb now holds pn^T
        transpose_kernel<<<tgrid, tblk>>>(Yb, (it == 9) ? out : Pb);
    }
    // z = out (row-major), z^T = Yb

    // ---- Alignments ----
    gemm_nn_big(T, ENC, T,
                out, T, TT,
                xh + (long)BT * ENC, ENC, (long)T * ENC,
                xal, ENC, (long)T * ENC, nullptr, 0, 0, B);
    gemm_nn_big(T, ENC, T,
                Yb, T, TT,
                xh, ENC, (long)T * ENC,
                xal + (long)BT * ENC, ENC, (long)T * ENC, nullptr, 0, 0, B);

    // ---- Compare projections ----
    gemm_nt_big(BT, H, ENC, xal, ENC, 0, Wp1, ENC, 0, xc, H, 0, bp1, 1, 0, 1);
    gemm_nt_big(BT, H, ENC, xh + (long)BT * ENC, ENC, 0, Wp2, 2 * ENC, 0,
                xc + (long)BT * H, H, 0, nullptr, 0, 0, 1);
    gemm_nt_big(BT, H, ENC, xal + (long)BT * ENC, ENC, 0, Wp2 + ENC, 2 * ENC, 0,
                xc + (long)BT * H, H, 0, bp2, 1, 1, 1);

    // ---- Layer-2 input projections (reuse Gproj) ----
    for (int s = 0; s < 2; s++) {
        gemm_nt_big(BT, G4, H, xc + (long)s * BT * H, H, 0,
                    Wih_mf, H, 0,
                    Gproj + (long)s * BT * (2 * G4), 2 * G4, 0, b_mf, 0, 0, 1);
        gemm_nt_big(BT, G4, H, xc + (long)s * BT * H, H, 0,
                    Wih_mb, H, 0,
                    Gproj + (long)s * BT * (2 * G4) + G4, 2 * G4, 0, b_mb, 0, 0, 1);
    }

    // ---- BiLSTM layer 2 ----
    {
        dim3 grid(B / BB, 2, 2);
        lstm_layer_kernel<<<grid, 256>>>(Gproj, Whh_mf, Whh_mb, xcomp);
    }

    // ---- Pooling + output ----
    pool_kernel<<<(2 * B * ENC + 255) / 256, 256>>>(xcomp, rep);
    final_kernel<<<B, 256>>>(rep, Wo, bo, out);
}

// round 4
// speedup vs baseline: 2.7249x; 2.7249x over previous
#include <cuda_runtime.h>
#include <cstdint>
#include <math.h>

// ---------------------------------------------------------------------------
// Problem constants
// ---------------------------------------------------------------------------
namespace cfg {
constexpr int B   = 64;
constexpr int T   = 256;
constexpr int E   = 300;
constexpr int H   = 200;
constexpr int BT  = B * T;        // 16384
constexpr int G4  = 4 * H;        // 800
constexpr int ENC = 2 * H;        // 400
constexpr long TT  = (long)T * T; // 65536
// LSTM v2 partition
constexpr int BB2 = 4;            // batch rows per block
constexpr int NB  = B / BB2;      // 16 batch groups
constexpr int HS  = 50;           // h outputs per slice
constexpr int NSL = H / HS;       // 4 slices
}
using namespace cfg;

// ---------------------------------------------------------------------------
// Static device scratch (allocation-free rule: __device__ globals)
// ---------------------------------------------------------------------------
__device__ float d_ebuf [2L * BT * E];
__device__ float d_Gproj[2L * BT * (2 * G4)];
__device__ float d_xh   [2L * BT * ENC];
__device__ float d_xcomp[2L * BT * ENC];
__device__ float d_xal  [2L * BT * ENC];
__device__ float d_xc   [2L * BT * H];
__device__ float d_P    [(long)B * T * T];
__device__ float d_Q1   [(long)B * T * T];
__device__ float d_Q2T  [(long)B * T * T];
__device__ float d_Ybuf [(long)B * T * T];
__device__ float d_YT   [(long)B * T * T];
__device__ float d_rep  [B * 4 * ENC];
// LSTM v2 state
__device__ float d_WTc  [2L * H * G4];     // transposed Whh (compose layer) [dir][k][g]
__device__ float d_WTm  [2L * H * G4];     // transposed Whh (merge layer)
__device__ float d_hbuf [2L * 4 * B * H];  // ping-pong h [par][ds][b][k]
__device__ int   d_cnt  [4 * NB];          // per (ds, bgroup) step counters

// ---------------------------------------------------------------------------
// Generic tiled SGEMM.  NT: C = A[M,K] @ B[N,K]^T.  NN: C = A[M,K] @ B[K,N].
// ---------------------------------------------------------------------------
template <int BM, int BN, int BK, int TM, int TN, bool NT>
__global__ void sgemm_kernel(int M, int N, int K,
                             const float* __restrict__ A, int lda, long sA,
                             const float* __restrict__ Bm, int ldb, long sB,
                             float* __restrict__ C, int ldc, long sC,
                             const float* __restrict__ bias, int relu, int accum)
{
    constexpr int TX = BN / TN;
    constexpr int TY = BM / TM;
    static_assert(TX * TY == 256, "256 threads");
    static_assert(TM == 8 && TN == 4, "vector micro-tile");
    __shared__ float As[BK][BM];
    __shared__ float Bs[BK][BN];

    int tid = threadIdx.x;
    int tx = tid % TX, ty = tid / TX;
    int m0 = blockIdx.y * BM, n0 = blockIdx.x * BN;
    A  += (long)blockIdx.z * sA;
    Bm += (long)blockIdx.z * sB;
    C  += (long)blockIdx.z * sC;

    float acc[TM][TN];
#pragma unroll
    for (int i = 0; i < TM; i++)
#pragma unroll
        for (int j = 0; j < TN; j++) acc[i][j] = 0.f;

    for (int k0 = 0; k0 < K; k0 += BK) {
        for (int idx = tid; idx < BM * BK; idx += 256) {
            int m = idx / BK, kk = idx % BK;
            int gm = m0 + m, gk = k0 + kk;
            As[kk][m] = (gm < M && gk < K) ? A[(long)gm * lda + gk] : 0.f;
        }
        if (NT) {
            for (int idx = tid; idx < BN * BK; idx += 256) {
                int n = idx / BK, kk = idx % BK;
                int gn = n0 + n, gk = k0 + kk;
                Bs[kk][n] = (gn < N && gk < K) ? Bm[(long)gn * ldb + gk] : 0.f;
            }
        } else {
            for (int idx = tid; idx < BN * BK; idx += 256) {
                int n = idx % BN, kk = idx / BN;
                int gn = n0 + n, gk = k0 + kk;
                Bs[kk][n] = (gn < N && gk < K) ? Bm[(long)gk * ldb + gn] : 0.f;
            }
        }
        __syncthreads();
#pragma unroll
        for (int kk = 0; kk < BK; kk++) {
            // vectorized, bank-conflict-free shared reads
            float4 a0 = *reinterpret_cast<const float4*>(&As[kk][ty * TM]);
            float4 a1 = *reinterpret_cast<const float4*>(&As[kk][ty * TM + 4]);
            float4 b0 = *reinterpret_cast<const float4*>(&Bs[kk][tx * TN]);
            float ra[TM] = {a0.x, a0.y, a0.z, a0.w, a1.x, a1.y, a1.z, a1.w};
            float rb[TN] = {b0.x, b0.y, b0.z, b0.w};
#pragma unroll
            for (int i = 0; i < TM; i++)
#pragma unroll
                for (int j = 0; j < TN; j++) acc[i][j] = fmaf(ra[i], rb[j], acc[i][j]);
        }
        __syncthreads();
    }

#pragma unroll
    for (int i = 0; i < TM; i++) {
        int gm = m0 + ty * TM + i;
        if (gm >= M) continue;
#pragma unroll
        for (int j = 0; j < TN; j++) {
            int gn = n0 + tx * TN + j;
            if (gn >= N) continue;
            float v = acc[i][j];
            long ci = (long)gm * ldc + gn;
            if (accum) v += C[ci];
            if (bias)  v += bias[gn];
            if (relu)  v = fmaxf(v, 0.f);
            C[ci] = v;
        }
    }
}

// ---------------------------------------------------------------------------
// Elementwise / small kernels
// ---------------------------------------------------------------------------
__global__ void embed_kernel(const int* __restrict__ x1, const int* __restrict__ x2,
                             const float* __restrict__ emb, float* __restrict__ ebuf)
{
    long idx = (long)blockIdx.x * blockDim.x + threadIdx.x;
    if (idx >= 2L * BT * E) return;
    int e = (int)(idx % E);
    long bt = (idx / E) % BT;
    int s = (int)(idx / ((long)E * BT));
    int tok = s ? x2[bt] : x1[bt];
    ebuf[idx] = emb[(long)tok * E + e];
}

// W[g][k] (both dirs) -> WT[dir][k][g]
__global__ void wtrans_kernel(const float* __restrict__ Wf, const float* __restrict__ Wb,
                              float* __restrict__ WT)
{
    int idx = blockIdx.x * blockDim.x + threadIdx.x;
    if (idx >= 2 * G4 * H) return;
    int dir = idx / (G4 * H);
    int r = idx % (G4 * H);
    int g = r / H, k = r % H;
    const float* W = dir ? Wb : Wf;
    WT[(long)dir * H * G4 + (long)k * G4 + g] = W[(long)g * H + k];
}

__global__ void reset_cnt_kernel()
{
    int i = threadIdx.x;
    if (i < 4 * NB) d_cnt[i] = 0;
}

__device__ __forceinline__ float sigmf(float x) { return 1.f / (1.f + expf(-x)); }

// ---------------------------------------------------------------------------
// Persistent BiLSTM layer v2.
// Grid: (NB=16 bgroups, NSL=4 h-slices, 4 ds=seq*2+dir), 256 threads.
// Each block: BB2=4 batch rows, HS=50 h-outputs (all 4 gate types), all T steps.
// h state ping-pongs through d_hbuf; the 4 slice-blocks of a (bgroup,ds) group
// sync per step via a fence + atomic counter. All 256 blocks are co-resident
// (256 thr, ~8 KB smem) so the spin barrier cannot deadlock.
// ---------------------------------------------------------------------------
__global__ __launch_bounds__(256, 6)
void lstm2_kernel(const float* __restrict__ Gproj,
                  const float* __restrict__ WTbase,
                  float* __restrict__ xh_out)
{
    __shared__ float h_sh[BB2][H];       // 3.2 KB
    __shared__ float g_sh[4][BB2][HS];   // 3.2 KB
    __shared__ float c_sh[BB2][HS];      // 800 B

    const int tid = threadIdx.x;
    const int b0  = blockIdx.x * BB2;
    const int hsl = blockIdx.y;
    const int ds  = blockIdx.z;
    const int d   = ds & 1;
    const int s   = ds >> 1;
    const int hh0 = hsl * HS;

    const float* WT = WTbase + (long)d * H * G4;
    float* hbuf = d_hbuf;
    int* cnt = &d_cnt[ds * NB + blockIdx.x];

    // matvec mapping: gate type + local h index
    const int mtype = tid / HS;          // 0..3 (valid if tid < 200)
    const int mj    = tid % HS;
    const int g     = mtype * H + hh0 + mj;   // column into WT
    const bool act  = (tid < 4 * HS);

    for (int i = tid; i < BB2 * HS; i += 256) (&c_sh[0][0])[i] = 0.f;
    __syncthreads();

    for (int t = 0; t < T; t++) {
        const int ta = d ? (T - 1 - t) : t;
        float acc0 = 0.f, acc1 = 0.f, acc2 = 0.f, acc3 = 0.f;

        if (t > 0) {
            // group barrier: wait until all 4 slice blocks finished step t-1
            if (tid == 0) {
                volatile int* c = cnt;
                while (*c < 4 * t) { __nanosleep(40); }
                __threadfence();
            }
            __syncthreads();
            // load full h(t) for our 4 batch rows
            const int par = t & 1;
            for (int i = tid; i < BB2 * H; i += 256) {
                int b = i / H, k = i % H;
                h_sh[b][k] = hbuf[(((long)par * 4 + ds) * B + b0 + b) * H + k];
            }
            __syncthreads();
            if (act) {
                for (int k = 0; k < H; k += 4) {
                    float w0 = WT[(k + 0) * G4 + g];
                    float w1 = WT[(k + 1) * G4 + g];
                    float w2 = WT[(k + 2) * G4 + g];
                    float w3 = WT[(k + 3) * G4 + g];
                    float4 h0 = *reinterpret_cast<const float4*>(&h_sh[0][k]);
                    float4 h1 = *reinterpret_cast<const float4*>(&h_sh[1][k]);
                    float4 h2 = *reinterpret_cast<const float4*>(&h_sh[2][k]);
                    float4 h3 = *reinterpret_cast<const float4*>(&h_sh[3][k]);
                    acc0 += w0 * h0.x + w1 * h0.y + w2 * h0.z + w3 * h0.w;
                    acc1 += w0 * h1.x + w1 * h1.y + w2 * h1.z + w3 * h1.w;
                    acc2 += w0 * h2.x + w1 * h2.y + w2 * h2.z + w3 * h2.w;
                    acc3 += w0 * h3.x + w1 * h3.y + w2 * h3.z + w3 * h3.w;
                }
            }
        }

        if (act) {
            // add precomputed input projections (bias folded in)
            long gbase = ((long)s * BT + (long)b0 * T + ta) * (2 * G4) + (long)d * G4 + g;
            g_sh[mtype][0][mj] = acc0 + Gproj[gbase];
            g_sh[mtype][1][mj] = acc1 + Gproj[gbase + (long)T * 2 * G4];
            g_sh[mtype][2][mj] = acc2 + Gproj[gbase + 2L * T * 2 * G4];
            g_sh[mtype][3][mj] = acc3 + Gproj[gbase + 3L * T * 2 * G4];
        }
        __syncthreads();

        if (act) {
            int b = tid / HS, j = tid % HS;
            float gi = g_sh[0][b][j];
            float gf = g_sh[1][b][j];
            float gg = g_sh[2][b][j];
            float go = g_sh[3][b][j];
            float cn = sigmf(gf) * c_sh[b][j] + sigmf(gi) * tanhf(gg);
            float hn = sigmf(go) * tanhf(cn);
            c_sh[b][j] = cn;
            hbuf[((((long)(t + 1) & 1) * 4 + ds) * B + b0 + b) * H + hh0 + j] = hn;
            xh_out[((long)s * BT + (long)(b0 + b) * T + ta) * ENC + d * H + hh0 + j] = hn;
        }
        __threadfence();
        __syncthreads();
        if (tid == 0) atomicAdd(cnt, 1);
    }
}

// ---------------------------------------------------------------------------
// Capped-simplex row projection (mirrors reference math exactly).
// ---------------------------------------------------------------------------
__global__ void proj_row_kernel(const float* __restrict__ P,
                                const float* __restrict__ Qin,
                                float* __restrict__ Y,
                                float* __restrict__ Qout,
                                int use_q)
{
    __shared__ float srt[T];
    __shared__ float cs[T];
    __shared__ float warp_s[8];
    __shared__ int   warp_c[8];
    __shared__ float sh_tau;

    int row = blockIdx.x;
    int j = threadIdx.x;
    long off = (long)row * T + j;

    float val = P[off];
    if (use_q) val += Qin[off];
    srt[j] = val;
    __syncthreads();

    for (int k = 2; k <= T; k <<= 1) {
        for (int jj = k >> 1; jj > 0; jj >>= 1) {
            int l = j ^ jj;
            if (l > j) {
                float a = srt[j], b2 = srt[l];
                bool desc = ((j & k) == 0);
                if (desc ? (a < b2) : (a > b2)) { srt[j] = b2; srt[l] = a; }
            }
            __syncthreads();
        }
    }

    cs[j] = srt[j];
    __syncthreads();
    for (int o = 1; o < T; o <<= 1) {
        float tv = (j >= o) ? cs[j - o] : 0.f;
        __syncthreads();
        cs[j] += tv;
        __syncthreads();
    }

    int lane = j & 31, wid = j >> 5;
    float u = fmaxf(val, 0.f);
#pragma unroll
    for (int o = 16; o; o >>= 1) u += __shfl_down_sync(0xffffffffu, u, o);
    bool fl = (1.f + (float)(j + 1) * srt[j]) > cs[j];
    unsigned bal = __ballot_sync(0xffffffffu, fl);
    if (lane == 0) { warp_s[wid] = u; warp_c[wid] = __popc(bal); }
    __syncthreads();
    if (j == 0) {
        float ssum = 0.f; int kmax = 0;
#pragma unroll
        for (int w = 0; w < 8; w++) { ssum += warp_s[w]; kmax += warp_c[w]; }
        float tau = 0.f;
        if (ssum > 1.f) tau = (cs[kmax - 1] - 1.f) / (float)kmax;
        sh_tau = tau;
    }
    __syncthreads();

    float y = fmaxf(val - sh_tau, 0.f);
    Y[off] = y;
    Qout[off] = val - y;
}

__global__ void transpose_kernel(const float* __restrict__ in, float* __restrict__ out)
{
    __shared__ float tile[32][33];
    long base = (long)blockIdx.z * TT;
    int i0 = blockIdx.y * 32, j0 = blockIdx.x * 32;
#pragma unroll
    for (int r = 0; r < 4; r++) {
        int i = i0 + threadIdx.y + r * 8;
        tile[threadIdx.y + r * 8][threadIdx.x] = in[base + (long)i * T + j0 + threadIdx.x];
    }
    __syncthreads();
#pragma unroll
    for (int r = 0; r < 4; r++) {
        int jj = j0 + threadIdx.y + r * 8;
        out[base + (long)jj * T + i0 + threadIdx.x] = tile[threadIdx.x][threadIdx.y + r * 8];
    }
}

__global__ void pool_kernel(const float* __restrict__ xcomp, float* __restrict__ rep)
{
    int idx = blockIdx.x * blockDim.x + threadIdx.x;
    if (idx >= 2 * B * ENC) return;
    int f = idx % ENC;
    int b = (idx / ENC) % B;
    int s = idx / (ENC * B);
    const float* base = xcomp + ((long)s * BT + (long)b * T) * ENC + f;
    float mx = -3.4e38f, sm = 0.f;
    for (int t = 0; t < T; t++) {
        float v = base[(long)t * ENC];
        sm += v;
        mx = fmaxf(mx, v);
    }
    rep[(long)b * (4 * ENC) + s * (2 * ENC) + f]       = sm * (1.f / (float)T);
    rep[(long)b * (4 * ENC) + s * (2 * ENC) + ENC + f] = mx;
}

__global__ void final_kernel(const float* __restrict__ rep, const float* __restrict__ Wo,
                             const float* __restrict__ bo, float* __restrict__ out)
{
    __shared__ float red[256];
    int b = blockIdx.x, tid = threadIdx.x;
    float s = 0.f;
    for (int i = tid; i < 4 * ENC; i += 256) s += rep[(long)b * (4 * ENC) + i] * Wo[i];
    red[tid] = s;
    __syncthreads();
    for (int o = 128; o; o >>= 1) {
        if (tid < o) red[tid] += red[tid + o];
        __syncthreads();
    }
    if (tid == 0) out[(long)B * TT + b] = 1.f / (1.f + expf(-(red[0] + bo[0])));
}

// ---------------------------------------------------------------------------
// Host launch helpers
// ---------------------------------------------------------------------------
static void gemm_nt_big(int M, int N, int K,
                        const float* A, int lda, long sA,
                        const float* Bm, int ldb, long sB,
                        float* C, int ldc, long sC,
                        const float* bias, int relu, int accum, int batch)
{
    dim3 grid((N + 63) / 64, (M + 127) / 128, batch);
    sgemm_kernel<128, 64, 16, 8, 4, true><<<grid, 256>>>(M, N, K, A, lda, sA, Bm, ldb, sB, C, ldc, sC, bias, relu, accum);
}
static void gemm_nn_big(int M, int N, int K,
                        const float* A, int lda, long sA,
                        const float* Bm, int ldb, long sB,
                        float* C, int ldc, long sC,
                        const float* bias, int relu, int accum, int batch)
{
    dim3 grid((N + 63) / 64, (M + 127) / 128, batch);
    sgemm_kernel<128, 64, 16, 8, 4, false><<<grid, 256>>>(M, N, K, A, lda, sA, Bm, ldb, sB, C, ldc, sC, bias, relu, accum);
}

// ---------------------------------------------------------------------------
// kernel_launch
// ---------------------------------------------------------------------------
extern "C" void kernel_launch(void* const* d_in, const int* in_sizes, int n_in,
                              void* d_out, int out_size)
{
    const int*   x1     = (const int*)d_in[0];
    const int*   x2     = (const int*)d_in[1];
    const float* embed  = (const float*)d_in[4];
    const float* Wih_cf = (const float*)d_in[5];
    const float* Whh_cf = (const float*)d_in[6];
    const float* b_cf   = (const float*)d_in[7];
    const float* Wih_cb = (const float*)d_in[8];
    const float* Whh_cb = (const float*)d_in[9];
    const float* b_cb   = (const float*)d_in[10];
    const float* Wp1    = (const float*)d_in[11];
    const float* bp1    = (const float*)d_in[12];
    const float* Wp2    = (const float*)d_in[13];
    const float* bp2    = (const float*)d_in[14];
    const float* Wih_mf = (const float*)d_in[15];
    const float* Whh_mf = (const float*)d_in[16];
    const float* b_mf   = (const float*)d_in[17];
    const float* Wih_mb = (const float*)d_in[18];
    const float* Whh_mb = (const float*)d_in[19];
    const float* b_mb   = (const float*)d_in[20];
    const float* Wo     = (const float*)d_in[21];
    const float* bo     = (const float*)d_in[22];
    float* out = (float*)d_out;

    void* p;
    cudaGetSymbolAddress(&p, d_ebuf);  float* ebuf  = (float*)p;
    cudaGetSymbolAddress(&p, d_Gproj); float* Gproj = (float*)p;
    cudaGetSymbolAddress(&p, d_xh);    float* xh    = (float*)p;
    cudaGetSymbolAddress(&p, d_xcomp); float* xcomp = (float*)p;
    cudaGetSymbolAddress(&p, d_xal);   float* xal   = (float*)p;
    cudaGetSymbolAddress(&p, d_xc);    float* xc    = (float*)p;
    cudaGetSymbolAddress(&p, d_P);     float* Pb    = (float*)p;
    cudaGetSymbolAddress(&p, d_Q1);    float* Q1    = (float*)p;
    cudaGetSymbolAddress(&p, d_Q2T);   float* Q2T   = (float*)p;
    cudaGetSymbolAddress(&p, d_Ybuf);  float* Yb    = (float*)p;
    cudaGetSymbolAddress(&p, d_YT);    float* YTb   = (float*)p;
    cudaGetSymbolAddress(&p, d_rep);   float* rep   = (float*)p;
    cudaGetSymbolAddress(&p, d_WTc);   float* WTc   = (float*)p;
    cudaGetSymbolAddress(&p, d_WTm);   float* WTm   = (float*)p;

    // ---- Weight transposes (both layers) + embedding ----
    {
        int n = 2 * G4 * H;
        wtrans_kernel<<<(n + 255) / 256, 256>>>(Whh_cf, Whh_cb, WTc);
        wtrans_kernel<<<(n + 255) / 256, 256>>>(Whh_mf, Whh_mb, WTm);
        long ne = 2L * BT * E;
        embed_kernel<<<(int)((ne + 255) / 256), 256>>>(x1, x2, embed, ebuf);
    }

    // ---- Layer-1 input projections: Gproj[s][bt][d*800 + g] ----
    for (int s = 0; s < 2; s++) {
        gemm_nt_big(BT, G4, E, ebuf + (long)s * BT * E, E, 0,
                    Wih_cf, E, 0,
                    Gproj + (long)s * BT * (2 * G4), 2 * G4, 0, b_cf, 0, 0, 1);
        gemm_nt_big(BT, G4, E, ebuf + (long)s * BT * E, E, 0,
                    Wih_cb, E, 0,
                    Gproj + (long)s * BT * (2 * G4) + G4, 2 * G4, 0, b_cb, 0, 0, 1);
    }

    // ---- BiLSTM layer 1 ----
    {
        reset_cnt_kernel<<<1, 64>>>();
        dim3 grid(NB, NSL, 4);
        lstm2_kernel<<<grid, 256>>>(Gproj, WTc, xh);
    }

    // ---- Scores: batched x1_h @ x2_h^T -> d_P ----
    gemm_nt_big(T, T, ENC,
                xh, ENC, (long)T * ENC,
                xh + (long)BT * ENC, ENC, (long)T * ENC,
                Pb, T, TT, nullptr, 0, 0, B);

    // ---- Dykstra (10 iterations) ----
    dim3 tgrid(8, 8, B), tblk(32, 8);
    for (int it = 0; it < 10; it++) {
        proj_row_kernel<<<BT, 256>>>(Pb, Q1, Yb, Q1, it > 0);
        transpose_kernel<<<tgrid, tblk>>>(Yb, YTb);
        proj_row_kernel<<<BT, 256>>>(YTb, Q2T, Yb, Q2T, it > 0);
        transpose_kernel<<<tgrid, tblk>>>(Yb, (it == 9) ? out : Pb);
    }
    // z = out (row-major), z^T = Yb

    // ---- Alignments ----
    gemm_nn_big(T, ENC, T,
                out, T, TT,
                xh + (long)BT * ENC, ENC, (long)T * ENC,
                xal, ENC, (long)T * ENC, nullptr, 0, 0, B);
    gemm_nn_big(T, ENC, T,
                Yb, T, TT,
                xh, ENC, (long)T * ENC,
                xal + (long)BT * ENC, ENC, (long)T * ENC, nullptr, 0, 0, B);

    // ---- Compare projections ----
    gemm_nt_big(BT, H, ENC, xal, ENC, 0, Wp1, ENC, 0, xc, H, 0, bp1, 1, 0, 1);
    gemm_nt_big(BT, H, ENC, xh + (long)BT * ENC, ENC, 0, Wp2, 2 * ENC, 0,
                xc + (long)BT * H, H, 0, nullptr, 0, 0, 1);
    gemm_nt_big(BT, H, ENC, xal + (long)BT * ENC, ENC, 0, Wp2 + ENC, 2 * ENC, 0,
                xc + (long)BT * H, H, 0, bp2, 1, 1, 1);

    // ---- Layer-2 input projections ----
    for (int s = 0; s < 2; s++) {
        gemm_nt_big(BT, G4, H, xc + (long)s * BT * H, H, 0,
                    Wih_mf, H, 0,
                    Gproj + (long)s * BT * (2 * G4), 2 * G4, 0, b_mf, 0, 0, 1);
        gemm_nt_big(BT, G4, H, xc + (long)s * BT * H, H, 0,
                    Wih_mb, H, 0,
                    Gproj + (long)s * BT * (2 * G4) + G4, 2 * G4, 0, b_mb, 0, 0, 1);
    }

    // ---- BiLSTM layer 2 ----
    {
        reset_cnt_kernel<<<1, 64>>>();
        dim3 grid(NB, NSL, 4);
        lstm2_kernel<<<grid, 256>>>(Gproj, WTm, xcomp);
    }

    // ---- Pooling + output ----
    pool_kernel<<<(2 * B * ENC + 255) / 256, 256>>>(xcomp, rep);
    final_kernel<<<B, 256>>>(rep, Wo, bo, out);
}

// round 6
// speedup vs baseline: 2.9625x; 1.0872x over previous
#include <cuda_runtime.h>
#include <cstdint>
#include <math.h>

// ---------------------------------------------------------------------------
// Problem constants
// ---------------------------------------------------------------------------
namespace cfg {
constexpr int B   = 64;
constexpr int T   = 256;
constexpr int E   = 300;
constexpr int H   = 200;
constexpr int BT  = B * T;        // 16384
constexpr int G4  = 4 * H;        // 800
constexpr int G8  = 2 * G4;       // 1600 (both dirs packed)
constexpr int ENC = 2 * H;        // 400
constexpr long TT  = (long)T * T; // 65536
// LSTM partition
constexpr int BB2 = 4;            // batch rows per block
constexpr int NB  = B / BB2;      // 16 batch groups
constexpr int HS  = 50;           // h outputs per slice
constexpr int NSL = H / HS;       // 4 slices
}
using namespace cfg;

// ---------------------------------------------------------------------------
// Static device scratch
// ---------------------------------------------------------------------------
__device__ float d_ebuf [2L * BT * E];
__device__ float d_Gproj[2L * BT * G8];
__device__ float d_xh   [2L * BT * ENC];
__device__ float d_xcomp[2L * BT * ENC];
__device__ float d_xal  [2L * BT * ENC];
__device__ float d_xc   [2L * BT * H];
__device__ float d_P    [(long)B * T * T];
__device__ float d_Q1   [(long)B * T * T];
__device__ float d_Q2T  [(long)B * T * T];
__device__ float d_Ybuf [(long)B * T * T];
__device__ float d_YT   [(long)B * T * T];
__device__ float d_rep  [B * 4 * ENC];
// LSTM state
__device__ float d_WTc  [2L * H * G4];
__device__ float d_WTm  [2L * H * G4];
__device__ float d_hbuf [2L * 4 * B * H];
__device__ int   d_cnt  [4 * NB];
// packed input-projection weights
__device__ float d_WPc  [G8 * E];
__device__ float d_WPm  [G8 * H];
__device__ float d_bpc  [G8];
__device__ float d_bpm  [G8];

// ---------------------------------------------------------------------------
// fp32x2 packed-FMA helpers (Blackwell PTX path; not emitted by ptxas from C++)
// ---------------------------------------------------------------------------
__device__ __forceinline__ void fma2(unsigned long long& d,
                                     unsigned long long a, unsigned long long b)
{
    asm("fma.rn.f32x2 %0, %1, %2, %0;" : "+l"(d) : "l"(a), "l"(b));
}
__device__ __forceinline__ unsigned long long pack2(float x, float y)
{
    unsigned long long r;
    asm("mov.b64 %0, {%1, %2};" : "=l"(r) : "f"(x), "f"(y));
    return r;
}
__device__ __forceinline__ float2 unpack2(unsigned long long v)
{
    float2 f;
    asm("mov.b64 {%0, %1}, %2;" : "=f"(f.x), "=f"(f.y) : "l"(v));
    return f;
}

// ---------------------------------------------------------------------------
// SGEMM 128x128x16, 8x8 microtile, fp32x2 inner loop.
// NT: C = A[M,K] @ B[N,K]^T.   NN: C = A[M,K] @ B[K,N].
// ---------------------------------------------------------------------------
template <bool NT>
__global__ __launch_bounds__(256, 2)
void sgemm128_kernel(int M, int N, int K,
                     const float* __restrict__ A, int lda, long sA,
                     const float* __restrict__ Bm, int ldb, long sB,
                     float* __restrict__ C, int ldc, long sC,
                     const float* __restrict__ bias, int relu, int accum)
{
    constexpr int BM = 128, BN = 128, BK = 16;
    __shared__ __align__(16) float As[BK][BM];
    __shared__ __align__(16) float Bs[BK][BN];

    const int tid = threadIdx.x;
    const int tx = tid % 16, ty = tid / 16;
    const int m0 = blockIdx.y * BM, n0 = blockIdx.x * BN;
    A  += (long)blockIdx.z * sA;
    Bm += (long)blockIdx.z * sB;
    C  += (long)blockIdx.z * sC;

    unsigned long long acc2[8][4];
#pragma unroll
    for (int i = 0; i < 8; i++)
#pragma unroll
        for (int j = 0; j < 4; j++) acc2[i][j] = 0ull;

    for (int k0 = 0; k0 < K; k0 += BK) {
#pragma unroll
        for (int r = 0; r < 8; r++) {
            int idx = tid + r * 256;
            int m = idx >> 4, kk = idx & 15;
            int gm = m0 + m, gk = k0 + kk;
            As[kk][m] = (gm < M && gk < K) ? A[(long)gm * lda + gk] : 0.f;
        }
        if (NT) {
#pragma unroll
            for (int r = 0; r < 8; r++) {
                int idx = tid + r * 256;
                int n = idx >> 4, kk = idx & 15;
                int gn = n0 + n, gk = k0 + kk;
                Bs[kk][n] = (gn < N && gk < K) ? Bm[(long)gn * ldb + gk] : 0.f;
            }
        } else {
            // 2048 elements = 256 threads x 8 passes: idx spans all (kk, n)
#pragma unroll
            for (int r = 0; r < 8; r++) {
                int idx = tid + r * 256;
                int n = idx & 127, kk = idx >> 7;   // kk in 0..15
                int gn = n0 + n, gk = k0 + kk;
                Bs[kk][n] = (gn < N && gk < K) ? Bm[(long)gk * ldb + gn] : 0.f;
            }
        }
        __syncthreads();

#pragma unroll
        for (int kk = 0; kk < BK; kk++) {
            const float4* A4 = reinterpret_cast<const float4*>(&As[kk][ty * 8]);
            float4 a0 = A4[0], a1 = A4[1];
            const ulonglong2* B2 = reinterpret_cast<const ulonglong2*>(&Bs[kk][tx * 8]);
            ulonglong2 bb0 = B2[0], bb1 = B2[1];
            unsigned long long bp0 = bb0.x, bp1 = bb0.y, bp2 = bb1.x, bp3 = bb1.y;
            float ra[8] = {a0.x, a0.y, a0.z, a0.w, a1.x, a1.y, a1.z, a1.w};
#pragma unroll
            for (int i = 0; i < 8; i++) {
                unsigned long long ap = pack2(ra[i], ra[i]);
                fma2(acc2[i][0], ap, bp0);
                fma2(acc2[i][1], ap, bp1);
                fma2(acc2[i][2], ap, bp2);
                fma2(acc2[i][3], ap, bp3);
            }
        }
        __syncthreads();
    }

#pragma unroll
    for (int i = 0; i < 8; i++) {
        int gm = m0 + ty * 8 + i;
        if (gm >= M) continue;
#pragma unroll
        for (int jp = 0; jp < 4; jp++) {
            float2 v2 = unpack2(acc2[i][jp]);
            int gn = n0 + tx * 8 + jp * 2;
#pragma unroll
            for (int u = 0; u < 2; u++) {
                int gnn = gn + u;
                if (gnn >= N) continue;
                float v = u ? v2.y : v2.x;
                long ci = (long)gm * ldc + gnn;
                if (accum) v += C[ci];
                if (bias)  v += bias[gnn];
                if (relu)  v = fmaxf(v, 0.f);
                C[ci] = v;
            }
        }
    }
}

// ---------------------------------------------------------------------------
// Elementwise / small kernels
// ---------------------------------------------------------------------------
__global__ void embed_kernel(const int* __restrict__ x1, const int* __restrict__ x2,
                             const float* __restrict__ emb, float* __restrict__ ebuf)
{
    long idx = (long)blockIdx.x * blockDim.x + threadIdx.x;
    if (idx >= 2L * BT * E) return;
    int e = (int)(idx % E);
    long bt = (idx / E) % BT;
    int s = (int)(idx / ((long)E * BT));
    int tok = s ? x2[bt] : x1[bt];
    ebuf[idx] = emb[(long)tok * E + e];
}

// W[g][k] (both dirs) -> WT[dir][k][g]
__global__ void wtrans_kernel(const float* __restrict__ Wf, const float* __restrict__ Wb,
                              float* __restrict__ WT)
{
    int idx = blockIdx.x * blockDim.x + threadIdx.x;
    if (idx >= 2 * G4 * H) return;
    int dir = idx / (G4 * H);
    int r = idx % (G4 * H);
    int g = r / H, k = r % H;
    const float* W = dir ? Wb : Wf;
    WT[(long)dir * H * G4 + (long)k * G4 + g] = W[(long)g * H + k];
}

// pack [Wf; Wb] -> WP[1600][K], [bf; bb] -> bp[1600]
__global__ void packw_kernel(const float* __restrict__ Wf, const float* __restrict__ Wb,
                             const float* __restrict__ bf, const float* __restrict__ bb,
                             float* __restrict__ WP, float* __restrict__ bp, int K)
{
    int idx = blockIdx.x * blockDim.x + threadIdx.x;
    if (idx < G8) {
        int d = idx / G4, g = idx % G4;
        bp[idx] = d ? bb[g] : bf[g];
    }
    int total = G8 * K;
    for (int i = idx; i < total; i += gridDim.x * blockDim.x) {
        int r = i / K, k = i % K;
        int d = r / G4, g = r % G4;
        const float* W = d ? Wb : Wf;
        WP[(long)r * K + k] = W[(long)g * K + k];
    }
}

__global__ void reset_cnt_kernel()
{
    int i = threadIdx.x;
    if (i < 4 * NB) d_cnt[i] = 0;
}

__device__ __forceinline__ float sigmf(float x) { return 1.f / (1.f + expf(-x)); }

// ---------------------------------------------------------------------------
// Persistent BiLSTM layer (grid 256 blocks, all co-resident; spin barrier)
// ---------------------------------------------------------------------------
__global__ __launch_bounds__(256, 6)
void lstm2_kernel(const float* __restrict__ Gproj,
                  const float* __restrict__ WTbase,
                  float* __restrict__ xh_out)
{
    __shared__ float h_sh[BB2][H];
    __shared__ float g_sh[4][BB2][HS];
    __shared__ float c_sh[BB2][HS];

    const int tid = threadIdx.x;
    const int b0  = blockIdx.x * BB2;
    const int hsl = blockIdx.y;
    const int ds  = blockIdx.z;
    const int d   = ds & 1;
    const int s   = ds >> 1;
    const int hh0 = hsl * HS;

    const float* WT = WTbase + (long)d * H * G4;
    float* hbuf = d_hbuf;
    int* cnt = &d_cnt[ds * NB + blockIdx.x];

    const int mtype = tid / HS;
    const int mj    = tid % HS;
    const int g     = mtype * H + hh0 + mj;
    const bool act  = (tid < 4 * HS);

    for (int i = tid; i < BB2 * HS; i += 256) (&c_sh[0][0])[i] = 0.f;
    __syncthreads();

    for (int t = 0; t < T; t++) {
        const int ta = d ? (T - 1 - t) : t;
        float acc0 = 0.f, acc1 = 0.f, acc2 = 0.f, acc3 = 0.f;

        if (t > 0) {
            if (tid == 0) {
                volatile int* c = cnt;
                while (*c < 4 * t) { __nanosleep(40); }
                __threadfence();
            }
            __syncthreads();
            const int par = t & 1;
            for (int i = tid; i < BB2 * H; i += 256) {
                int b = i / H, k = i % H;
                h_sh[b][k] = hbuf[(((long)par * 4 + ds) * B + b0 + b) * H + k];
            }
            __syncthreads();
            if (act) {
                for (int k = 0; k < H; k += 4) {
                    float w0 = WT[(k + 0) * G4 + g];
                    float w1 = WT[(k + 1) * G4 + g];
                    float w2 = WT[(k + 2) * G4 + g];
                    float w3 = WT[(k + 3) * G4 + g];
                    float4 h0 = *reinterpret_cast<const float4*>(&h_sh[0][k]);
                    float4 h1 = *reinterpret_cast<const float4*>(&h_sh[1][k]);
                    float4 h2 = *reinterpret_cast<const float4*>(&h_sh[2][k]);
                    float4 h3 = *reinterpret_cast<const float4*>(&h_sh[3][k]);
                    acc0 += w0 * h0.x + w1 * h0.y + w2 * h0.z + w3 * h0.w;
                    acc1 += w0 * h1.x + w1 * h1.y + w2 * h1.z + w3 * h1.w;
                    acc2 += w0 * h2.x + w1 * h2.y + w2 * h2.z + w3 * h2.w;
                    acc3 += w0 * h3.x + w1 * h3.y + w2 * h3.z + w3 * h3.w;
                }
            }
        }

        if (act) {
            long gbase = ((long)s * BT + (long)b0 * T + ta) * G8 + (long)d * G4 + g;
            g_sh[mtype][0][mj] = acc0 + Gproj[gbase];
            g_sh[mtype][1][mj] = acc1 + Gproj[gbase + (long)T * G8];
            g_sh[mtype][2][mj] = acc2 + Gproj[gbase + 2L * T * G8];
            g_sh[mtype][3][mj] = acc3 + Gproj[gbase + 3L * T * G8];
        }
        __syncthreads();

        if (act) {
            int b = tid / HS, j = tid % HS;
            float gi = g_sh[0][b][j];
            float gf = g_sh[1][b][j];
            float gg = g_sh[2][b][j];
            float go = g_sh[3][b][j];
            float cn = sigmf(gf) * c_sh[b][j] + sigmf(gi) * tanhf(gg);
            float hn = sigmf(go) * tanhf(cn);
            c_sh[b][j] = cn;
            hbuf[((((long)(t + 1) & 1) * 4 + ds) * B + b0 + b) * H + hh0 + j] = hn;
            xh_out[((long)s * BT + (long)(b0 + b) * T + ta) * ENC + d * H + hh0 + j] = hn;
        }
        __threadfence();
        __syncthreads();
        if (tid == 0) atomicAdd(cnt, 1);
    }
}

// ---------------------------------------------------------------------------
// Capped-simplex row projection (mirrors reference math exactly).
// ---------------------------------------------------------------------------
__global__ void proj_row_kernel(const float* __restrict__ P,
                                const float* __restrict__ Qin,
                                float* __restrict__ Y,
                                float* __restrict__ Qout,
                                int use_q)
{
    __shared__ float srt[T];
    __shared__ float cs[T];
    __shared__ float warp_s[8];
    __shared__ int   warp_c[8];
    __shared__ float sh_tau;

    int row = blockIdx.x;
    int j = threadIdx.x;
    long off = (long)row * T + j;

    float val = P[off];
    if (use_q) val += Qin[off];
    srt[j] = val;
    __syncthreads();

    for (int k = 2; k <= T; k <<= 1) {
        for (int jj = k >> 1; jj > 0; jj >>= 1) {
            int l = j ^ jj;
            if (l > j) {
                float a = srt[j], b2 = srt[l];
                bool desc = ((j & k) == 0);
                if (desc ? (a < b2) : (a > b2)) { srt[j] = b2; srt[l] = a; }
            }
            __syncthreads();
        }
    }

    cs[j] = srt[j];
    __syncthreads();
    for (int o = 1; o < T; o <<= 1) {
        float tv = (j >= o) ? cs[j - o] : 0.f;
        __syncthreads();
        cs[j] += tv;
        __syncthreads();
    }

    int lane = j & 31, wid = j >> 5;
    float u = fmaxf(val, 0.f);
#pragma unroll
    for (int o = 16; o; o >>= 1) u += __shfl_down_sync(0xffffffffu, u, o);
    bool fl = (1.f + (float)(j + 1) * srt[j]) > cs[j];
    unsigned bal = __ballot_sync(0xffffffffu, fl);
    if (lane == 0) { warp_s[wid] = u; warp_c[wid] = __popc(bal); }
    __syncthreads();
    if (j == 0) {
        float ssum = 0.f; int kmax = 0;
#pragma unroll
        for (int w = 0; w < 8; w++) { ssum += warp_s[w]; kmax += warp_c[w]; }
        float tau = 0.f;
        if (ssum > 1.f) tau = (cs[kmax - 1] - 1.f) / (float)kmax;
        sh_tau = tau;
    }
    __syncthreads();

    float y = fmaxf(val - sh_tau, 0.f);
    Y[off] = y;
    Qout[off] = val - y;
}

__global__ void transpose_kernel(const float* __restrict__ in, float* __restrict__ out)
{
    __shared__ float tile[32][33];
    long base = (long)blockIdx.z * TT;
    int i0 = blockIdx.y * 32, j0 = blockIdx.x * 32;
#pragma unroll
    for (int r = 0; r < 4; r++) {
        int i = i0 + threadIdx.y + r * 8;
        tile[threadIdx.y + r * 8][threadIdx.x] = in[base + (long)i * T + j0 + threadIdx.x];
    }
    __syncthreads();
#pragma unroll
    for (int r = 0; r < 4; r++) {
        int jj = j0 + threadIdx.y + r * 8;
        out[base + (long)jj * T + i0 + threadIdx.x] = tile[threadIdx.x][threadIdx.y + r * 8];
    }
}

__global__ void pool_kernel(const float* __restrict__ xcomp, float* __restrict__ rep)
{
    int idx = blockIdx.x * blockDim.x + threadIdx.x;
    if (idx >= 2 * B * ENC) return;
    int f = idx % ENC;
    int b = (idx / ENC) % B;
    int s = idx / (ENC * B);
    const float* base = xcomp + ((long)s * BT + (long)b * T) * ENC + f;
    float mx = -3.4e38f, sm = 0.f;
    for (int t = 0; t < T; t++) {
        float v = base[(long)t * ENC];
        sm += v;
        mx = fmaxf(mx, v);
    }
    rep[(long)b * (4 * ENC) + s * (2 * ENC) + f]       = sm * (1.f / (float)T);
    rep[(long)b * (4 * ENC) + s * (2 * ENC) + ENC + f] = mx;
}

__global__ void final_kernel(const float* __restrict__ rep, const float* __restrict__ Wo,
                             const float* __restrict__ bo, float* __restrict__ out)
{
    __shared__ float red[256];
    int b = blockIdx.x, tid = threadIdx.x;
    float s = 0.f;
    for (int i = tid; i < 4 * ENC; i += 256) s += rep[(long)b * (4 * ENC) + i] * Wo[i];
    red[tid] = s;
    __syncthreads();
    for (int o = 128; o; o >>= 1) {
        if (tid < o) red[tid] += red[tid + o];
        __syncthreads();
    }
    if (tid == 0) out[(long)B * TT + b] = 1.f / (1.f + expf(-(red[0] + bo[0])));
}

// ---------------------------------------------------------------------------
// Host launch helpers
// ---------------------------------------------------------------------------
static void gemm_nt(int M, int N, int K,
                    const float* A, int lda, long sA,
                    const float* Bm, int ldb, long sB,
                    float* C, int ldc, long sC,
                    const float* bias, int relu, int accum, int batch)
{
    dim3 grid((N + 127) / 128, (M + 127) / 128, batch);
    sgemm128_kernel<true><<<grid, 256>>>(M, N, K, A, lda, sA, Bm, ldb, sB, C, ldc, sC, bias, relu, accum);
}
static void gemm_nn(int M, int N, int K,
                    const float* A, int lda, long sA,
                    const float* Bm, int ldb, long sB,
                    float* C, int ldc, long sC,
                    const float* bias, int relu, int accum, int batch)
{
    dim3 grid((N + 127) / 128, (M + 127) / 128, batch);
    sgemm128_kernel<false><<<grid, 256>>>(M, N, K, A, lda, sA, Bm, ldb, sB, C, ldc, sC, bias, relu, accum);
}

// ---------------------------------------------------------------------------
// kernel_launch
// ---------------------------------------------------------------------------
extern "C" void kernel_launch(void* const* d_in, const int* in_sizes, int n_in,
                              void* d_out, int out_size)
{
    const int*   x1     = (const int*)d_in[0];
    const int*   x2     = (const int*)d_in[1];
    const float* embed  = (const float*)d_in[4];
    const float* Wih_cf = (const float*)d_in[5];
    const float* Whh_cf = (const float*)d_in[6];
    const float* b_cf   = (const float*)d_in[7];
    const float* Wih_cb = (const float*)d_in[8];
    const float* Whh_cb = (const float*)d_in[9];
    const float* b_cb   = (const float*)d_in[10];
    const float* Wp1    = (const float*)d_in[11];
    const float* bp1    = (const float*)d_in[12];
    const float* Wp2    = (const float*)d_in[13];
    const float* bp2    = (const float*)d_in[14];
    const float* Wih_mf = (const float*)d_in[15];
    const float* Whh_mf = (const float*)d_in[16];
    const float* b_mf   = (const float*)d_in[17];
    const float* Wih_mb = (const float*)d_in[18];
    const float* Whh_mb = (const float*)d_in[19];
    const float* b_mb   = (const float*)d_in[20];
    const float* Wo     = (const float*)d_in[21];
    const float* bo     = (const float*)d_in[22];
    float* out = (float*)d_out;

    void* p;
    cudaGetSymbolAddress(&p, d_ebuf);  float* ebuf  = (float*)p;
    cudaGetSymbolAddress(&p, d_Gproj); float* Gproj = (float*)p;
    cudaGetSymbolAddress(&p, d_xh);    float* xh    = (float*)p;
    cudaGetSymbolAddress(&p, d_xcomp); float* xcomp = (float*)p;
    cudaGetSymbolAddress(&p, d_xal);   float* xal   = (float*)p;
    cudaGetSymbolAddress(&p, d_xc);    float* xc    = (float*)p;
    cudaGetSymbolAddress(&p, d_P);     float* Pb    = (float*)p;
    cudaGetSymbolAddress(&p, d_Q1);    float* Q1    = (float*)p;
    cudaGetSymbolAddress(&p, d_Q2T);   float* Q2T   = (float*)p;
    cudaGetSymbolAddress(&p, d_Ybuf);  float* Yb    = (float*)p;
    cudaGetSymbolAddress(&p, d_YT);    float* YTb   = (float*)p;
    cudaGetSymbolAddress(&p, d_rep);   float* rep   = (float*)p;
    cudaGetSymbolAddress(&p, d_WTc);   float* WTc   = (float*)p;
    cudaGetSymbolAddress(&p, d_WTm);   float* WTm   = (float*)p;
    cudaGetSymbolAddress(&p, d_WPc);   float* WPc   = (float*)p;
    cudaGetSymbolAddress(&p, d_WPm);   float* WPm   = (float*)p;
    cudaGetSymbolAddress(&p, d_bpc);   float* bpc   = (float*)p;
    cudaGetSymbolAddress(&p, d_bpm);   float* bpm   = (float*)p;

    // ---- Weight transposes / packing + embedding ----
    {
        int n = 2 * G4 * H;
        wtrans_kernel<<<(n + 255) / 256, 256>>>(Whh_cf, Whh_cb, WTc);
        wtrans_kernel<<<(n + 255) / 256, 256>>>(Whh_mf, Whh_mb, WTm);
        packw_kernel<<<512, 256>>>(Wih_cf, Wih_cb, b_cf, b_cb, WPc, bpc, E);
        packw_kernel<<<512, 256>>>(Wih_mf, Wih_mb, b_mf, b_mb, WPm, bpm, H);
        long ne = 2L * BT * E;
        embed_kernel<<<(int)((ne + 255) / 256), 256>>>(x1, x2, embed, ebuf);
    }

    // ---- Layer-1 input projections (packed, 2 GEMMs) ----
    for (int s = 0; s < 2; s++) {
        gemm_nt(BT, G8, E, ebuf + (long)s * BT * E, E, 0,
                WPc, E, 0,
                Gproj + (long)s * BT * G8, G8, 0, bpc, 0, 0, 1);
    }

    // ---- BiLSTM layer 1 ----
    {
        reset_cnt_kernel<<<1, 64>>>();
        dim3 grid(NB, NSL, 4);
        lstm2_kernel<<<grid, 256>>>(Gproj, WTc, xh);
    }

    // ---- Scores ----
    gemm_nt(T, T, ENC,
            xh, ENC, (long)T * ENC,
            xh + (long)BT * ENC, ENC, (long)T * ENC,
            Pb, T, TT, nullptr, 0, 0, B);

    // ---- Dykstra (10 iterations) ----
    dim3 tgrid(8, 8, B), tblk(32, 8);
    for (int it = 0; it < 10; it++) {
        proj_row_kernel<<<BT, 256>>>(Pb, Q1, Yb, Q1, it > 0);
        transpose_kernel<<<tgrid, tblk>>>(Yb, YTb);
        proj_row_kernel<<<BT, 256>>>(YTb, Q2T, Yb, Q2T, it > 0);
        transpose_kernel<<<tgrid, tblk>>>(Yb, (it == 9) ? out : Pb);
    }
    // z = out, z^T = Yb

    // ---- Alignments ----
    gemm_nn(T, ENC, T,
            out, T, TT,
            xh + (long)BT * ENC, ENC, (long)T * ENC,
            xal, ENC, (long)T * ENC, nullptr, 0, 0, B);
    gemm_nn(T, ENC, T,
            Yb, T, TT,
            xh, ENC, (long)T * ENC,
            xal + (long)BT * ENC, ENC, (long)T * ENC, nullptr, 0, 0, B);

    // ---- Compare projections ----
    gemm_nt(BT, H, ENC, xal, ENC, 0, Wp1, ENC, 0, xc, H, 0, bp1, 1, 0, 1);
    gemm_nt(BT, H, ENC, xh + (long)BT * ENC, ENC, 0, Wp2, 2 * ENC, 0,
            xc + (long)BT * H, H, 0, nullptr, 0, 0, 1);
    gemm_nt(BT, H, ENC, xal + (long)BT * ENC, ENC, 0, Wp2 + ENC, 2 * ENC, 0,
            xc + (long)BT * H, H, 0, bp2, 1, 1, 1);

    // ---- Layer-2 input projections (packed, 2 GEMMs) ----
    for (int s = 0; s < 2; s++) {
        gemm_nt(BT, G8, H, xc + (long)s * BT * H, H, 0,
                WPm, H, 0,
                Gproj + (long)s * BT * G8, G8, 0, bpm, 0, 0, 1);
    }

    // ---- BiLSTM layer 2 ----
    {
        reset_cnt_kernel<<<1, 64>>>();
        dim3 grid(NB, NSL, 4);
        lstm2_kernel<<<grid, 256>>>(Gproj, WTm, xcomp);
    }

    // ---- Pooling + output ----
    pool_kernel<<<(2 * B * ENC + 255) / 256, 256>>>(xcomp, rep);
    final_kernel<<<B, 256>>>(rep, Wo, bo, out);
}